// round 15
// baseline (speedup 1.0000x reference)
#include <cuda_runtime.h>
#include <cstdint>

#define NB 16
#define NA 200000
#define NK 300
#define NKP 320        // padded box array (lane reads up to wi*32+31 = 319)
#define CAP 16384
#define FCAP 2048
#define NW 10          // ceil(300/32) mask words
#define NBINS 2048
#define FULLM 0xffffffffu
#define SEL_BLKS 8     // select blocks per batch (grid 128 <= 148 SMs, one wave)
#define SCAN_F4_TOTAL 800000
#define SCAN_F4_BLK 1024     // f4 per scan block (256 thr x 4)
#define STG 512              // smem staging entries

typedef unsigned long long ull;

// Scratch (no allocations). Zero-init at load; NMS-runner resets per replay.
__device__ int g_count[NB];
__device__ int g_done2[NB];
__device__ unsigned g_hist[NB][NBINS];
__device__ ull g_cand[NB * CAP];
__device__ unsigned g_mask[NB][NK * NW];   // triangular words rewritten every run

__device__ __forceinline__ int bin_of(unsigned sbits) {
    return min((int)((sbits >> 12) - 0x3F000u), NBINS - 1);
}

// ---------------------------------------------------------------------------
// Pass 1 (R13-proven): streaming scan, 4 independent float4 loads per thread.
// sigmoid(x)>=0.5 <=> x>=0; precise sigmoid only for positives.
// Per-thread smem atomics (cheap at ~94/block); two opposing stacks for the
// (at most one) batch boundary per block. No warp collectives.
// ---------------------------------------------------------------------------
__global__ void k_scan(const float4* __restrict__ conf4) {
    __shared__ int scnt[2];
    __shared__ int sbase[2];
    __shared__ ull stage[STG];
    const int t = threadIdx.x;
    if (t < 2) scnt[t] = 0;
    __syncthreads();

    const int base4 = blockIdx.x * SCAN_F4_BLK;
    const int b0 = (base4 * 4) / NA;
    const int split = (b0 + 1) * NA;

    // Front-batched independent loads.
    float4 v[4];
    #pragma unroll
    for (int q = 0; q < 4; q++) {
        int gi = base4 + q * 256 + t;
        v[q] = (gi < SCAN_F4_TOTAL) ? conf4[gi]
                                    : make_float4(-1.f, -1.f, -1.f, -1.f);
    }

    #pragma unroll
    for (int q = 0; q < 4; q++) {
        int gi4 = (base4 + q * 256 + t) * 4;
        float xs[4] = {v[q].x, v[q].y, v[q].z, v[q].w};
        #pragma unroll
        for (int e = 0; e < 4; e++) {
            if (xs[e] >= 0.0f) {
                int idx = gi4 + e;
                int sel = (idx >= split) ? 1 : 0;
                unsigned a = (unsigned)(idx - (b0 + sel) * NA);
                float s = 1.0f / (1.0f + expf(-xs[e]));
                unsigned sbits = __float_as_uint(s);
                ull key = ((ull)sbits << 32) | (ull)(0xFFFFFFFFu - a);
                atomicAdd(&g_hist[b0 + sel][bin_of(sbits)], 1u);
                int p = atomicAdd(&scnt[sel], 1);
                int slot = sel ? (STG - 1 - p) : p;
                if (p < STG / 2 + STG / 4)
                    stage[slot] = key;
            }
        }
    }
    __syncthreads();
    int n0 = min(scnt[0], STG);
    int n1 = min(scnt[1], STG);
    if (t < 2) {
        int n = t ? n1 : n0;
        sbase[t] = n ? atomicAdd(&g_count[b0 + t], n) : 0;
    }
    __syncthreads();
    for (int i = t; i < n0; i += 256) {
        int p = sbase[0] + i;
        if (p < CAP) g_cand[b0 * CAP + p] = stage[i];
    }
    for (int i = t; i < n1; i += 256) {
        int p = sbase[1] + i;
        if (p < CAP) g_cand[(b0 + 1) * CAP + p] = stage[STG - 1 - i];
    }
}

// ---------------------------------------------------------------------------
// Pass 2: 8 blocks per batch (grid = 128, one wave).
// Front in all 8 (redundant): key PREFETCH overlapping suffix-scan ->
// register compact -> counting-rank sort (LDS.128 pairs) -> decode.
// Mask build split by j%8==c -> g_mask. Last arriver: NMS + outputs + reset.
// ---------------------------------------------------------------------------
__device__ __forceinline__ void bitonic_desc(ull* a, int N, int tid) {
    for (int k = 2; k <= N; k <<= 1) {
        for (int j = k >> 1; j > 0; j >>= 1) {
            for (int i = tid; i < N; i += 1024) {
                int ixj = i ^ j;
                if (ixj > i) {
                    ull a0 = a[i], a1 = a[ixj];
                    bool up = ((i & k) == 0);
                    if ((a0 < a1) == up) { a[i] = a1; a[ixj] = a0; }
                }
            }
            __syncthreads();
        }
    }
}

__global__ void __launch_bounds__(1024, 1)
k_select(const float* __restrict__ p_loc,
         const float* __restrict__ anchors,
         float* __restrict__ out) {
    __shared__ __align__(16) ull cand2[FCAP];   // 16 KB
    __shared__ unsigned wsum[32];
    __shared__ int sT, scount2, schanged, s_flag;
    __shared__ int srank_hi[512];
    __shared__ ull sstage[NK];
    __shared__ float4 sbox[NKP];
    __shared__ float sarea[NKP];
    __shared__ float ssc[NK];
    __shared__ unsigned colmask[NK * NW];
    __shared__ unsigned svalid[NW];
    __shared__ unsigned kw[2][NW];

    const int tid = threadIdx.x;
    const int lane = tid & 31;
    const int wrp = tid >> 5;
    const unsigned ltm = (1u << lane) - 1u;
    const int b = blockIdx.x / SEL_BLKS;
    const int c = blockIdx.x % SEL_BLKS;

    int count = g_count[b];
    if (count > CAP) count = CAP;

    // Prefetch candidate keys into registers (overlaps the suffix-scan below).
    ull pref[5];
    const bool useP = (count <= 5120);
    if (useP) {
        #pragma unroll
        for (int k = 0; k < 5; k++) {
            int i = tid + k * 1024;
            pref[k] = (i < count) ? g_cand[b * CAP + i] : 0ULL;
        }
    }

    if (tid < NK) sstage[tid] = 0ULL;
    if (tid >= NK && tid < NKP) {
        sbox[tid] = make_float4(0.f, 0.f, 0.f, 0.f);
        sarea[tid] = 0.f;
    }
    if (tid == 0) { sT = 0; scount2 = 0; }

    // Suffix scan over histogram (2 bins/thread, reverse order) -> rank-NK bin.
    {
        int r0 = 2 * tid, r1 = 2 * tid + 1;
        unsigned h0 = g_hist[b][NBINS - 1 - r0];
        unsigned h1 = g_hist[b][NBINS - 1 - r1];
        unsigned tsum = h0 + h1;
        unsigned inc = tsum;
        #pragma unroll
        for (int o = 1; o < 32; o <<= 1) {
            unsigned nn = __shfl_up_sync(FULLM, inc, o);
            if (lane >= o) inc += nn;
        }
        if (lane == 31) wsum[wrp] = inc;
        __syncthreads();
        if (tid < 32) {
            unsigned w = wsum[tid];
            #pragma unroll
            for (int o = 1; o < 32; o <<= 1) {
                unsigned nn = __shfl_up_sync(FULLM, w, o);
                if (tid >= o) w += nn;
            }
            wsum[tid] = w;
        }
        __syncthreads();
        unsigned C0 = (wrp ? wsum[wrp - 1] : 0u) + (inc - tsum);
        unsigned C1 = C0 + h0;
        if (C0 < NK && C0 + h0 >= NK) sT = NBINS - 1 - r0;
        if (C1 < NK && C1 + h1 >= NK) sT = NBINS - 1 - r1;
    }
    __syncthreads();

    // Compact bin >= T. Register path (uniform 5 iters) or guarded fallback.
    {
        int T = sT;
        if (useP) {
            #pragma unroll
            for (int k = 0; k < 5; k++) {
                int i = tid + k * 1024;
                ull kk = pref[k];
                bool pred = (i < count) && (bin_of((unsigned)(kk >> 32)) >= T);
                unsigned m = __ballot_sync(FULLM, pred);
                if (pred) {
                    int leader = __ffs(m) - 1;
                    int base = 0;
                    if (lane == leader) base = atomicAdd(&scount2, __popc(m));
                    base = __shfl_sync(m, base, leader);
                    int p = base + __popc(m & ltm);
                    if (p < FCAP) cand2[p] = kk;
                }
            }
        } else {
            int countP = (count + 1023) & ~1023;
            for (int i = tid; i < countP; i += 1024) {
                ull kk = 0; bool pred = false;
                if (i < count) {
                    kk = g_cand[b * CAP + i];
                    pred = (bin_of((unsigned)(kk >> 32)) >= T);
                }
                unsigned m = __ballot_sync(FULLM, pred);
                if (pred) {
                    int leader = __ffs(m) - 1;
                    int base = 0;
                    if (lane == leader) base = atomicAdd(&scount2, __popc(m));
                    base = __shfl_sync(m, base, leader);
                    int p = base + __popc(m & ltm);
                    if (p < FCAP) cand2[p] = kk;
                }
            }
        }
    }
    __syncthreads();
    int count2 = min(scount2, FCAP);

    // Counting-rank sort (keys unique by construction). LDS.128 pairs.
    const ulonglong2* c2 = (const ulonglong2*)cand2;
    if (count2 <= 512) {
        int half = count2 >> 1;
        ull my = 0; int rlo = 0;
        if (tid < count2) {
            my = cand2[tid];
            int np = half >> 1;
            for (int p = 0; p < np; p++) {
                ulonglong2 kk = c2[p];
                rlo += (kk.x > my) + (kk.y > my);
            }
            if (half & 1) rlo += (cand2[half - 1] > my);
        } else if (tid >= 512 && tid < 512 + count2) {
            ull m2 = cand2[tid - 512];
            int r = 0;
            int j = half;
            if (j & 1) { r += (cand2[j] > m2); j++; }
            for (; j + 2 <= count2; j += 2) {
                ulonglong2 kk = c2[j >> 1];
                r += (kk.x > m2) + (kk.y > m2);
            }
            if (j < count2) r += (cand2[j] > m2);
            srank_hi[tid - 512] = r;
        }
        __syncthreads();
        if (tid < count2) {
            int r = rlo + srank_hi[tid];
            if (r < NK) sstage[r] = my;
        }
        __syncthreads();
    } else if (count2 <= 1024) {
        if (tid < count2) {
            ull my = cand2[tid];
            int r = 0;
            int np = count2 >> 1;
            for (int p = 0; p < np; p++) {
                ulonglong2 kk = c2[p];
                r += (kk.x > my) + (kk.y > my);
            }
            if (count2 & 1) r += (cand2[count2 - 1] > my);
            if (r < NK) sstage[r] = my;
        }
        __syncthreads();
    } else {
        int N2 = 2048;
        for (int i = count2 + tid; i < N2; i += 1024) cand2[i] = 0ULL;
        __syncthreads();
        bitonic_desc(cand2, N2, tid);
        if (tid < NK) sstage[tid] = cand2[tid];
        __syncthreads();
    }

    // Decode boxes; svalid via ballot. (Identical in all 8 blocks.)
    {
        bool valid = false;
        float x1 = 0.f, y1 = 0.f, x2 = 0.f, y2 = 0.f, s = 0.f, area = 0.f;
        if (tid < NK) {
            ull key = sstage[tid];
            s = __uint_as_float((unsigned)(key >> 32));
            valid = (key != 0ULL);
            if (valid) {
                int a = (int)(0xFFFFFFFFu - (unsigned)(key & 0xFFFFFFFFu));
                float4 an = ((const float4*)anchors)[a];
                float4 lv = ((const float4*)p_loc)[(size_t)b * NA + a];
                float cx = an.x + lv.x * 0.1f * an.z;
                float cy = an.y + lv.y * 0.1f * an.w;
                float w = an.z * expf(lv.z * 0.2f);
                float h = an.w * expf(lv.w * 0.2f);
                x1 = cx - 0.5f * w; y1 = cy - 0.5f * h;
                x2 = cx + 0.5f * w; y2 = cy + 0.5f * h;
                area = fmaxf(x2 - x1, 0.f) * fmaxf(y2 - y1, 0.f);
            }
        }
        unsigned vb = __ballot_sync(FULLM, valid);
        if (lane == 0 && wrp < NW) svalid[wrp] = vb;
        if (tid < NK) {
            sbox[tid] = make_float4(x1, y1, x2, y2);
            sarea[tid] = area;
            ssc[tid] = s;
        }
    }
    __syncthreads();

    // Triangular mask build split 8 ways: this block does rows j%8==c.
    for (int j = c + 8 * wrp; j < NK; j += 256) {
        float4 bj = sbox[j];
        float ja = sarea[j];
        int wmax = j >> 5;
        for (int wi = 0; wi <= wmax; wi++) {
            int i = wi * 32 + lane;              // <= 319, padded range
            float4 bi = sbox[i];
            float lt0 = fmaxf(bi.x, bj.x), lt1 = fmaxf(bi.y, bj.y);
            float rb0 = fminf(bi.z, bj.z), rb1 = fminf(bi.w, bj.w);
            float iw = fmaxf(rb0 - lt0, 0.f), ih = fmaxf(rb1 - lt1, 0.f);
            float inter = iw * ih;
            float uni = fmaxf(sarea[i] + ja - inter, 1e-9f);
            bool sup = (i < j) && (inter > 0.3f * uni);
            unsigned m = __ballot_sync(FULLM, sup);
            if (lane == 0) g_mask[b][j * NW + wi] = m;
        }
    }

    // Release mask writes; last of 8 runs NMS + output.
    __threadfence();
    __syncthreads();
    if (tid == 0) {
        int a2 = atomicAdd(&g_done2[b], 1);
        s_flag = (a2 == SEL_BLKS - 1);
    }
    __syncthreads();
    if (!s_flag) return;
    __threadfence();   // acquire peers' g_mask writes

    // Pull masks into smem (only triangular words are read below).
    for (int i = tid; i < NK * NW; i += 1024) colmask[i] = g_mask[b][i];
    __syncthreads();

    // Parallel greedy NMS: fixed point of keep[j] = valid[j] & !exists(i<j kept, sup(i,j)).
    {
        if (tid < NW) kw[0][tid] = svalid[tid];
        __syncthreads();
        int cur = 0;
        bool myvalid = (tid < NK) && ((svalid[tid >> 5] >> (tid & 31)) & 1u);
        int mywmax = tid >> 5;
        for (int t = 0; t < NK + 2; t++) {
            if (tid == 0) schanged = 0;
            __syncthreads();
            bool kp = false;
            if (tid < NK) {
                unsigned sup = 0;
                for (int w = 0; w <= mywmax; w++)
                    sup |= colmask[tid * NW + w] & kw[cur][w];
                kp = myvalid && (sup == 0);
            }
            unsigned word = __ballot_sync(FULLM, kp);
            if (lane == 0 && wrp < NW) {
                kw[cur ^ 1][wrp] = word;
                if (word != kw[cur][wrp]) schanged = 1;
            }
            __syncthreads();
            if (!schanged) break;               // fixed point == greedy result
            cur ^= 1;
        }
        if (tid < NW) svalid[tid] = kw[cur][tid];
    }
    __syncthreads();

    // Outputs: [ids(4800) | boxes(19200) | labels(4800) | scores(4800) | keep(4800)]
    if (tid < NK) {
        bool keep = (svalid[tid >> 5] >> (tid & 31)) & 1u;
        int slot = b * NK + tid;
        float kf = keep ? 1.0f : 0.0f;
        float4 bx = sbox[tid];
        out[slot] = keep ? (float)b : -1.0f;
        float* ob = out + NB * NK + slot * 4;
        ob[0] = bx.x * kf;
        ob[1] = bx.y * kf;
        ob[2] = bx.z * kf;
        ob[3] = bx.w * kf;
        out[NB * NK * 5 + slot] = kf;
        out[NB * NK * 6 + slot] = ssc[tid] * kf;
        out[NB * NK * 7 + slot] = kf;
    }

    // Reset global scratch for next replay (module-load values also 0).
    for (int i = tid; i < NBINS; i += 1024) g_hist[b][i] = 0u;
    if (tid == 0) { g_count[b] = 0; g_done2[b] = 0; }
}

extern "C" void kernel_launch(void* const* d_in, const int* in_sizes, int n_in,
                              void* d_out, int out_size) {
    const float* p_loc   = (const float*)d_in[0];
    const float* p_conf  = (const float*)d_in[1];
    // d_in[2] = p_landms: dead compute in reference, intentionally unread.
    const float* anchors = (const float*)d_in[3];
    float* out = (float*)d_out;

    int scan_grid = (SCAN_F4_TOTAL + SCAN_F4_BLK - 1) / SCAN_F4_BLK;  // 782
    k_scan<<<scan_grid, 256>>>((const float4*)p_conf);
    k_select<<<NB * SEL_BLKS, 1024>>>(p_loc, anchors, out);
}

// round 16
// speedup vs baseline: 1.4028x; 1.4028x over previous
#include <cuda_runtime.h>
#include <cstdint>

#define NB 16
#define NA 200000
#define NK 300
#define NKP 320        // padded box array (lane reads up to wi*32+31 = 319)
#define CAP 16384
#define FCAP 2048
#define NW 10          // ceil(300/32) mask words
#define NBINS 2048
#define FULLM 0xffffffffu
#define SEL_BLKS 8     // select blocks per batch (grid 128 <= 148 SMs, one wave)

typedef unsigned long long ull;

// Scratch (no allocations). Zero-init at load; NMS-runner resets per replay.
__device__ int g_count[NB];
__device__ int g_done2[NB];
__device__ unsigned g_hist[NB][NBINS];
__device__ ull g_cand[NB * CAP];
__device__ unsigned g_mask[NB][NK * NW];   // triangular words rewritten every run

__device__ __forceinline__ int bin_of(unsigned sbits) {
    return min((int)((sbits >> 12) - 0x3F000u), NBINS - 1);
}

// ---------------------------------------------------------------------------
// Pass 1 (R12-proven, measured ~5.8us incl. launch): 3125 blocks x 256.
// sigmoid(x)>=0.5 <=> x>=0; precise sigmoid only for ~2.3% positives;
// per-batch histogram via global RED; one compacting atomicAdd per
// (block, batch). At most one batch boundary per 1024-elem block.
// ---------------------------------------------------------------------------
__global__ void k_scan(const float4* __restrict__ conf4) {
    __shared__ int scnt[2];
    __shared__ int sbase[2];
    const int t = threadIdx.x;
    if (t < 2) scnt[t] = 0;
    __syncthreads();

    int gi = blockIdx.x * 256 + t;           // float4 index (grid exact: 800000)
    float4 v = conf4[gi];
    int e0 = gi * 4;
    int b0 = (blockIdx.x * 1024) / NA;       // batch of first elem in block
    int split = (b0 + 1) * NA;               // first elem of next batch

    ull key[4]; int pos[4]; int sel[4]; bool pred[4];
    float xs[4] = {v.x, v.y, v.z, v.w};
    #pragma unroll
    for (int e = 0; e < 4; e++) {
        pred[e] = (xs[e] >= 0.0f);
        if (pred[e]) {
            int idx = e0 + e;
            sel[e] = (idx >= split) ? 1 : 0;
            unsigned a = (unsigned)(idx - (b0 + sel[e]) * NA);
            float s = 1.0f / (1.0f + expf(-xs[e]));
            unsigned sbits = __float_as_uint(s);
            key[e] = ((ull)sbits << 32) | (ull)(0xFFFFFFFFu - a);
            pos[e] = atomicAdd(&scnt[sel[e]], 1);
            atomicAdd(&g_hist[b0 + sel[e]][bin_of(sbits)], 1u);
        }
    }
    __syncthreads();
    if (t < 2) sbase[t] = scnt[t] ? atomicAdd(&g_count[b0 + t], scnt[t]) : 0;
    __syncthreads();
    #pragma unroll
    for (int e = 0; e < 4; e++) {
        if (pred[e]) {
            int p = sbase[sel[e]] + pos[e];
            if (p < CAP) g_cand[(b0 + sel[e]) * CAP + p] = key[e];
        }
    }
}

// ---------------------------------------------------------------------------
// Pass 2 (R13-proven, measured 18.9us): 8 blocks per batch (grid = 128).
// Redundant front in all 8: suffix-scan hist (rank 300) -> ballot compact
// (interleaved load+consume; NO front-batched prefetch) -> counting-rank
// sort -> decode boxes. Mask build split by j%8==c -> g_mask.
// Last arriver: load masks, fixed-point greedy NMS, outputs, reset scratch.
// ---------------------------------------------------------------------------
__device__ __forceinline__ void bitonic_desc(ull* a, int N, int tid) {
    for (int k = 2; k <= N; k <<= 1) {
        for (int j = k >> 1; j > 0; j >>= 1) {
            for (int i = tid; i < N; i += 1024) {
                int ixj = i ^ j;
                if (ixj > i) {
                    ull a0 = a[i], a1 = a[ixj];
                    bool up = ((i & k) == 0);
                    if ((a0 < a1) == up) { a[i] = a1; a[ixj] = a0; }
                }
            }
            __syncthreads();
        }
    }
}

__global__ void __launch_bounds__(1024, 1)
k_select(const float* __restrict__ p_loc,
         const float* __restrict__ anchors,
         float* __restrict__ out) {
    __shared__ __align__(16) ull cand2[FCAP];   // 16 KB
    __shared__ unsigned wsum[32];
    __shared__ int sT, scount2, schanged, s_flag;
    __shared__ int srank_hi[512];
    __shared__ ull sstage[NK];
    __shared__ float4 sbox[NKP];
    __shared__ float sarea[NKP];
    __shared__ float ssc[NK];
    __shared__ unsigned colmask[NK * NW];
    __shared__ unsigned svalid[NW];
    __shared__ unsigned kw[2][NW];

    const int tid = threadIdx.x;
    const int lane = tid & 31;
    const int wrp = tid >> 5;
    const unsigned ltm = (1u << lane) - 1u;
    const int b = blockIdx.x / SEL_BLKS;
    const int c = blockIdx.x % SEL_BLKS;

    int count = g_count[b];
    if (count > CAP) count = CAP;

    if (tid < NK) sstage[tid] = 0ULL;
    if (tid >= NK && tid < NKP) {
        sbox[tid] = make_float4(0.f, 0.f, 0.f, 0.f);
        sarea[tid] = 0.f;
    }
    if (tid == 0) { sT = 0; scount2 = 0; }

    // Suffix scan over histogram (2 bins/thread, reverse order) -> rank-NK bin.
    {
        int r0 = 2 * tid, r1 = 2 * tid + 1;
        unsigned h0 = g_hist[b][NBINS - 1 - r0];
        unsigned h1 = g_hist[b][NBINS - 1 - r1];
        unsigned tsum = h0 + h1;
        unsigned inc = tsum;
        #pragma unroll
        for (int o = 1; o < 32; o <<= 1) {
            unsigned nn = __shfl_up_sync(FULLM, inc, o);
            if (lane >= o) inc += nn;
        }
        if (lane == 31) wsum[wrp] = inc;
        __syncthreads();
        if (tid < 32) {
            unsigned w = wsum[tid];
            #pragma unroll
            for (int o = 1; o < 32; o <<= 1) {
                unsigned nn = __shfl_up_sync(FULLM, w, o);
                if (tid >= o) w += nn;
            }
            wsum[tid] = w;
        }
        __syncthreads();
        unsigned C0 = (wrp ? wsum[wrp - 1] : 0u) + (inc - tsum);
        unsigned C1 = C0 + h0;
        if (C0 < NK && C0 + h0 >= NK) sT = NBINS - 1 - r0;
        if (C1 < NK && C1 + h1 >= NK) sT = NBINS - 1 - r1;
    }
    __syncthreads();

    // Compact bin >= T (padded uniform loop, warp-aggregated atomics,
    // interleaved load+consume).
    {
        int T = sT;
        int countP = (count + 1023) & ~1023;
        for (int i = tid; i < countP; i += 1024) {
            ull k = 0; bool pred = false;
            if (i < count) {
                k = g_cand[b * CAP + i];
                pred = (bin_of((unsigned)(k >> 32)) >= T);
            }
            unsigned m = __ballot_sync(FULLM, pred);
            if (pred) {
                int leader = __ffs(m) - 1;
                int base = 0;
                if (lane == leader) base = atomicAdd(&scount2, __popc(m));
                base = __shfl_sync(m, base, leader);
                int p = base + __popc(m & ltm);
                if (p < FCAP) cand2[p] = k;
            }
        }
    }
    __syncthreads();
    int count2 = min(scount2, FCAP);

    // Counting-rank sort (keys unique by construction).
    if (count2 <= 512) {
        int half = count2 >> 1;
        ull my = 0; int rlo = 0;
        if (tid < count2) {
            my = cand2[tid];
            for (int j = 0; j < half; j++) rlo += (cand2[j] > my);
        } else if (tid >= 512 && tid < 512 + count2) {
            ull m2 = cand2[tid - 512];
            int r = 0;
            for (int j = half; j < count2; j++) r += (cand2[j] > m2);
            srank_hi[tid - 512] = r;
        }
        __syncthreads();
        if (tid < count2) {
            int r = rlo + srank_hi[tid];
            if (r < NK) sstage[r] = my;
        }
        __syncthreads();
    } else if (count2 <= 1024) {
        if (tid < count2) {
            ull my = cand2[tid];
            int r = 0;
            for (int j = 0; j < count2; j++) r += (cand2[j] > my);
            if (r < NK) sstage[r] = my;
        }
        __syncthreads();
    } else {
        int N2 = 2048;
        for (int i = count2 + tid; i < N2; i += 1024) cand2[i] = 0ULL;
        __syncthreads();
        bitonic_desc(cand2, N2, tid);
        if (tid < NK) sstage[tid] = cand2[tid];
        __syncthreads();
    }

    // Decode boxes; svalid via ballot. (Identical in all 8 blocks.)
    {
        bool valid = false;
        float x1 = 0.f, y1 = 0.f, x2 = 0.f, y2 = 0.f, s = 0.f, area = 0.f;
        if (tid < NK) {
            ull key = sstage[tid];
            s = __uint_as_float((unsigned)(key >> 32));
            valid = (key != 0ULL);
            if (valid) {
                int a = (int)(0xFFFFFFFFu - (unsigned)(key & 0xFFFFFFFFu));
                float4 an = ((const float4*)anchors)[a];
                float4 lv = ((const float4*)p_loc)[(size_t)b * NA + a];
                float cx = an.x + lv.x * 0.1f * an.z;
                float cy = an.y + lv.y * 0.1f * an.w;
                float w = an.z * expf(lv.z * 0.2f);
                float h = an.w * expf(lv.w * 0.2f);
                x1 = cx - 0.5f * w; y1 = cy - 0.5f * h;
                x2 = cx + 0.5f * w; y2 = cy + 0.5f * h;
                area = fmaxf(x2 - x1, 0.f) * fmaxf(y2 - y1, 0.f);
            }
        }
        unsigned vb = __ballot_sync(FULLM, valid);
        if (lane == 0 && wrp < NW) svalid[wrp] = vb;
        if (tid < NK) {
            sbox[tid] = make_float4(x1, y1, x2, y2);
            sarea[tid] = area;
            ssc[tid] = s;
        }
    }
    __syncthreads();

    // Triangular mask build split 8 ways: this block does rows j%8==c.
    for (int j = c + 8 * wrp; j < NK; j += 256) {
        float4 bj = sbox[j];
        float ja = sarea[j];
        int wmax = j >> 5;
        for (int wi = 0; wi <= wmax; wi++) {
            int i = wi * 32 + lane;              // <= 319, padded range
            float4 bi = sbox[i];
            float lt0 = fmaxf(bi.x, bj.x), lt1 = fmaxf(bi.y, bj.y);
            float rb0 = fminf(bi.z, bj.z), rb1 = fminf(bi.w, bj.w);
            float iw = fmaxf(rb0 - lt0, 0.f), ih = fmaxf(rb1 - lt1, 0.f);
            float inter = iw * ih;
            float uni = fmaxf(sarea[i] + ja - inter, 1e-9f);
            bool sup = (i < j) && (inter > 0.3f * uni);
            unsigned m = __ballot_sync(FULLM, sup);
            if (lane == 0) g_mask[b][j * NW + wi] = m;
        }
    }

    // Release mask writes; last of 8 runs NMS + output.
    __threadfence();
    __syncthreads();
    if (tid == 0) {
        int a2 = atomicAdd(&g_done2[b], 1);
        s_flag = (a2 == SEL_BLKS - 1);
    }
    __syncthreads();
    if (!s_flag) return;
    __threadfence();   // acquire peers' g_mask writes

    // Pull masks into smem (only triangular words are read below).
    for (int i = tid; i < NK * NW; i += 1024) colmask[i] = g_mask[b][i];
    __syncthreads();

    // Parallel greedy NMS: fixed point of keep[j] = valid[j] & !exists(i<j kept, sup(i,j)).
    {
        if (tid < NW) kw[0][tid] = svalid[tid];
        __syncthreads();
        int cur = 0;
        bool myvalid = (tid < NK) && ((svalid[tid >> 5] >> (tid & 31)) & 1u);
        int mywmax = tid >> 5;
        for (int t = 0; t < NK + 2; t++) {
            if (tid == 0) schanged = 0;
            __syncthreads();
            bool kp = false;
            if (tid < NK) {
                unsigned sup = 0;
                for (int w = 0; w <= mywmax; w++)
                    sup |= colmask[tid * NW + w] & kw[cur][w];
                kp = myvalid && (sup == 0);
            }
            unsigned word = __ballot_sync(FULLM, kp);
            if (lane == 0 && wrp < NW) {
                kw[cur ^ 1][wrp] = word;
                if (word != kw[cur][wrp]) schanged = 1;
            }
            __syncthreads();
            if (!schanged) break;               // fixed point == greedy result
            cur ^= 1;
        }
        if (tid < NW) svalid[tid] = kw[cur][tid];
    }
    __syncthreads();

    // Outputs: [ids(4800) | boxes(19200) | labels(4800) | scores(4800) | keep(4800)]
    if (tid < NK) {
        bool keep = (svalid[tid >> 5] >> (tid & 31)) & 1u;
        int slot = b * NK + tid;
        float kf = keep ? 1.0f : 0.0f;
        float4 bx = sbox[tid];
        out[slot] = keep ? (float)b : -1.0f;
        float* ob = out + NB * NK + slot * 4;
        ob[0] = bx.x * kf;
        ob[1] = bx.y * kf;
        ob[2] = bx.z * kf;
        ob[3] = bx.w * kf;
        out[NB * NK * 5 + slot] = kf;
        out[NB * NK * 6 + slot] = ssc[tid] * kf;
        out[NB * NK * 7 + slot] = kf;
    }

    // Reset global scratch for next replay (module-load values also 0).
    for (int i = tid; i < NBINS; i += 1024) g_hist[b][i] = 0u;
    if (tid == 0) { g_count[b] = 0; g_done2[b] = 0; }
}

extern "C" void kernel_launch(void* const* d_in, const int* in_sizes, int n_in,
                              void* d_out, int out_size) {
    const float* p_loc   = (const float*)d_in[0];
    const float* p_conf  = (const float*)d_in[1];
    // d_in[2] = p_landms: dead compute in reference, intentionally unread.
    const float* anchors = (const float*)d_in[3];
    float* out = (float*)d_out;

    k_scan<<<(NB * NA / 4) / 256, 256>>>((const float4*)p_conf);
    k_select<<<NB * SEL_BLKS, 1024>>>(p_loc, anchors, out);
}

// round 17
// speedup vs baseline: 1.6936x; 1.2073x over previous
#include <cuda_runtime.h>
#include <cstdint>

#define NB 16
#define NA 200000
#define NK 300
#define NKP 320        // padded box array (lane reads up to wi*32+31 = 319)
#define CAP 16384
#define FCAP 2048
#define NW 10          // ceil(300/32) mask words
#define NBINS 2048
#define FULLM 0xffffffffu
#define SEL_BLKS 8     // select blocks per batch (grid 128 <= 148 SMs, one wave)

typedef unsigned long long ull;

// Scratch (no allocations). Zero-init at load; NMS-runner resets per replay.
__device__ int g_count[NB];
__device__ int g_done2[NB];
__device__ unsigned g_hist[NB][NBINS];
__device__ ull g_cand[NB * CAP];
__device__ unsigned g_mask[NB][NK * NW];   // triangular words rewritten every run

__device__ __forceinline__ int bin_of(unsigned sbits) {
    return min((int)((sbits >> 12) - 0x3F000u), NBINS - 1);
}

// ---------------------------------------------------------------------------
// Pass 1 (R12-proven): 3125 blocks x 256. sigmoid(x)>=0.5 <=> x>=0; precise
// sigmoid only for ~2.3% positives; per-batch histogram via global RED; one
// compacting atomicAdd per (block, batch).
// ---------------------------------------------------------------------------
__global__ void k_scan(const float4* __restrict__ conf4) {
    __shared__ int scnt[2];
    __shared__ int sbase[2];
    const int t = threadIdx.x;
    if (t < 2) scnt[t] = 0;
    __syncthreads();

    int gi = blockIdx.x * 256 + t;           // float4 index (grid exact: 800000)
    float4 v = conf4[gi];
    int e0 = gi * 4;
    int b0 = (blockIdx.x * 1024) / NA;       // batch of first elem in block
    int split = (b0 + 1) * NA;               // first elem of next batch

    ull key[4]; int pos[4]; int sel[4]; bool pred[4];
    float xs[4] = {v.x, v.y, v.z, v.w};
    #pragma unroll
    for (int e = 0; e < 4; e++) {
        pred[e] = (xs[e] >= 0.0f);
        if (pred[e]) {
            int idx = e0 + e;
            sel[e] = (idx >= split) ? 1 : 0;
            unsigned a = (unsigned)(idx - (b0 + sel[e]) * NA);
            float s = 1.0f / (1.0f + expf(-xs[e]));
            unsigned sbits = __float_as_uint(s);
            key[e] = ((ull)sbits << 32) | (ull)(0xFFFFFFFFu - a);
            pos[e] = atomicAdd(&scnt[sel[e]], 1);
            atomicAdd(&g_hist[b0 + sel[e]][bin_of(sbits)], 1u);
        }
    }
    __syncthreads();
    if (t < 2) sbase[t] = scnt[t] ? atomicAdd(&g_count[b0 + t], scnt[t]) : 0;
    __syncthreads();
    #pragma unroll
    for (int e = 0; e < 4; e++) {
        if (pred[e]) {
            int p = sbase[sel[e]] + pos[e];
            if (p < CAP) g_cand[(b0 + sel[e]) * CAP + p] = key[e];
        }
    }
}

// ---------------------------------------------------------------------------
// Pass 2: 8 blocks per batch (grid = 128). Redundant front in all 8:
//   suffix-scan hist -> per-bin C offsets in sC -> DIRECT SCATTER of the
//   ~302 threshold-passing keys (rank = C(bin) + within-bin refine) ->
//   decode boxes. Mask build split by j%8==c -> g_mask.
// Last arriver: fixed-point greedy NMS (reads g_mask directly), outputs,
// scratch reset. Bitonic fallback if stot > 512.
// ---------------------------------------------------------------------------
__device__ __forceinline__ void bitonic_desc(ull* a, int N, int tid) {
    for (int k = 2; k <= N; k <<= 1) {
        for (int j = k >> 1; j > 0; j >>= 1) {
            for (int i = tid; i < N; i += 1024) {
                int ixj = i ^ j;
                if (ixj > i) {
                    ull a0 = a[i], a1 = a[ixj];
                    bool up = ((i & k) == 0);
                    if ((a0 < a1) == up) { a[i] = a1; a[ixj] = a0; }
                }
            }
            __syncthreads();
        }
    }
}

__global__ void __launch_bounds__(1024, 1)
k_select(const float* __restrict__ p_loc,
         const float* __restrict__ anchors,
         float* __restrict__ out) {
    __shared__ __align__(16) ull cand2[FCAP];   // 16 KB (scatter buf / bitonic fallback)
    __shared__ unsigned sC[NBINS];              // 8 KB per-bin rank offsets
    __shared__ unsigned wsum[32];
    __shared__ int sT, stot_s, scount2, schanged, s_flag;
    __shared__ ull sstage[NK];
    __shared__ float4 sbox[NKP];
    __shared__ float sarea[NKP];
    __shared__ float ssc[NK];
    __shared__ unsigned svalid[NW];
    __shared__ unsigned kw[2][NW];

    const int tid = threadIdx.x;
    const int lane = tid & 31;
    const int wrp = tid >> 5;
    const unsigned ltm = (1u << lane) - 1u;
    const int b = blockIdx.x / SEL_BLKS;
    const int c = blockIdx.x % SEL_BLKS;

    int count = g_count[b];
    if (count > CAP) count = CAP;

    if (tid < NK) sstage[tid] = 0ULL;
    if (tid >= NK && tid < NKP) {
        sbox[tid] = make_float4(0.f, 0.f, 0.f, 0.f);
        sarea[tid] = 0.f;
    }
    if (tid == 0) { sT = 0; stot_s = 0; scount2 = 0; }

    // Suffix scan over histogram (2 bins/thread, reverse order).
    // Produces: sT (rank-NK bin), stot (keys in bins >= T), sC[bin] = C(bin).
    {
        int r0 = 2 * tid, r1 = 2 * tid + 1;
        int b0 = NBINS - 1 - r0, b1 = NBINS - 1 - r1;
        unsigned h0 = g_hist[b][b0];
        unsigned h1 = g_hist[b][b1];
        unsigned tsum = h0 + h1;
        unsigned inc = tsum;
        #pragma unroll
        for (int o = 1; o < 32; o <<= 1) {
            unsigned nn = __shfl_up_sync(FULLM, inc, o);
            if (lane >= o) inc += nn;
        }
        if (lane == 31) wsum[wrp] = inc;
        __syncthreads();
        if (tid < 32) {
            unsigned w = wsum[tid];
            #pragma unroll
            for (int o = 1; o < 32; o <<= 1) {
                unsigned nn = __shfl_up_sync(FULLM, w, o);
                if (tid >= o) w += nn;
            }
            wsum[tid] = w;
        }
        __syncthreads();
        unsigned C0 = (wrp ? wsum[wrp - 1] : 0u) + (inc - tsum);  // keys in bins > b0
        unsigned C1 = C0 + h0;                                    // keys in bins > b1
        sC[b0] = C0;
        sC[b1] = C1;
        if (C0 < NK && C0 + h0 >= NK) { sT = b0; stot_s = (int)(C0 + h0); }
        if (C1 < NK && C1 + h1 >= NK) { sT = b1; stot_s = (int)(C1 + h1); }
        // total < NK: no thread fires -> T=0; runner fixes stot below.
    }
    __syncthreads();
    int T = sT;
    int stot = stot_s;
    if (stot == 0) stot = min((int)sC[0] + (int)g_hist[b][0], NK + 512); // tiny-count case

    if (stot <= 512) {
        // Direct scatter: each passing key takes slot = C(bin) + arrival order.
        for (int i = tid; i < count; i += 1024) {
            ull k = g_cand[b * CAP + i];
            int bn = bin_of((unsigned)(k >> 32));
            if (bn >= T) {
                unsigned slot = atomicAdd(&sC[bn], 1u);
                cand2[slot] = k;                 // slot < stot <= 512 guaranteed
            }
        }
        __syncthreads();
        // Refine intra-bin order: rank = binstart + #{same-bin keys > mine}.
        if (tid < stot) {
            ull k = cand2[tid];
            int bn = bin_of((unsigned)(k >> 32));
            int l = tid;
            while (l > 0 && bin_of((unsigned)(cand2[l - 1] >> 32)) == bn) l--;
            int rank = l;
            for (; l < stot; l++) {
                ull o = cand2[l];
                if (bin_of((unsigned)(o >> 32)) != bn) break;
                rank += (o > k);
            }
            if (rank < NK) sstage[rank] = k;
        }
        __syncthreads();
    } else {
        // Pathological fallback: ballot compact + bitonic (uniform padded loop).
        int countP = (count + 1023) & ~1023;
        for (int i = tid; i < countP; i += 1024) {
            ull k = 0; bool pred = false;
            if (i < count) {
                k = g_cand[b * CAP + i];
                pred = (bin_of((unsigned)(k >> 32)) >= T);
            }
            unsigned m = __ballot_sync(FULLM, pred);
            if (pred) {
                int leader = __ffs(m) - 1;
                int base = 0;
                if (lane == leader) base = atomicAdd(&scount2, __popc(m));
                base = __shfl_sync(m, base, leader);
                int p = base + __popc(m & ltm);
                if (p < FCAP) cand2[p] = k;
            }
        }
        __syncthreads();
        int count2 = min(scount2, FCAP);
        int N2 = 1024;
        while (N2 < count2) N2 <<= 1;            // <= FCAP
        for (int i = count2 + tid; i < N2; i += 1024) cand2[i] = 0ULL;
        __syncthreads();
        bitonic_desc(cand2, N2, tid);
        if (tid < NK) sstage[tid] = cand2[tid];
        __syncthreads();
    }

    // Decode boxes; svalid via ballot. (Identical in all 8 blocks.)
    {
        bool valid = false;
        float x1 = 0.f, y1 = 0.f, x2 = 0.f, y2 = 0.f, s = 0.f, area = 0.f;
        if (tid < NK) {
            ull key = sstage[tid];
            s = __uint_as_float((unsigned)(key >> 32));
            valid = (key != 0ULL);
            if (valid) {
                int a = (int)(0xFFFFFFFFu - (unsigned)(key & 0xFFFFFFFFu));
                float4 an = ((const float4*)anchors)[a];
                float4 lv = ((const float4*)p_loc)[(size_t)b * NA + a];
                float cx = an.x + lv.x * 0.1f * an.z;
                float cy = an.y + lv.y * 0.1f * an.w;
                float w = an.z * expf(lv.z * 0.2f);
                float h = an.w * expf(lv.w * 0.2f);
                x1 = cx - 0.5f * w; y1 = cy - 0.5f * h;
                x2 = cx + 0.5f * w; y2 = cy + 0.5f * h;
                area = fmaxf(x2 - x1, 0.f) * fmaxf(y2 - y1, 0.f);
            }
        }
        unsigned vb = __ballot_sync(FULLM, valid);
        if (lane == 0 && wrp < NW) svalid[wrp] = vb;
        if (tid < NK) {
            sbox[tid] = make_float4(x1, y1, x2, y2);
            sarea[tid] = area;
            ssc[tid] = s;
        }
    }
    __syncthreads();

    // Triangular mask build split 8 ways: this block does rows j%8==c.
    for (int j = c + 8 * wrp; j < NK; j += 256) {
        float4 bj = sbox[j];
        float ja = sarea[j];
        int wmax = j >> 5;
        for (int wi = 0; wi <= wmax; wi++) {
            int i = wi * 32 + lane;              // <= 319, padded range
            float4 bi = sbox[i];
            float lt0 = fmaxf(bi.x, bj.x), lt1 = fmaxf(bi.y, bj.y);
            float rb0 = fminf(bi.z, bj.z), rb1 = fminf(bi.w, bj.w);
            float iw = fmaxf(rb0 - lt0, 0.f), ih = fmaxf(rb1 - lt1, 0.f);
            float inter = iw * ih;
            float uni = fmaxf(sarea[i] + ja - inter, 1e-9f);
            bool sup = (i < j) && (inter > 0.3f * uni);
            unsigned m = __ballot_sync(FULLM, sup);
            if (lane == 0) g_mask[b][j * NW + wi] = m;
        }
    }

    // Release mask writes; last of 8 runs NMS + output.
    __threadfence();
    __syncthreads();
    if (tid == 0) {
        int a2 = atomicAdd(&g_done2[b], 1);
        s_flag = (a2 == SEL_BLKS - 1);
    }
    __syncthreads();
    if (!s_flag) return;
    __threadfence();   // acquire peers' g_mask writes

    // Parallel greedy NMS: fixed point of keep[j] = valid[j] & !exists(i<j kept, sup(i,j)).
    // Reads g_mask directly (L1-resident after the first iteration).
    {
        if (tid < NW) kw[0][tid] = svalid[tid];
        __syncthreads();
        int cur = 0;
        bool myvalid = (tid < NK) && ((svalid[tid >> 5] >> (tid & 31)) & 1u);
        int mywmax = tid >> 5;
        const unsigned* mrow = &g_mask[b][tid * NW];
        for (int t = 0; t < NK + 2; t++) {
            if (tid == 0) schanged = 0;
            __syncthreads();
            bool kp = false;
            if (tid < NK) {
                unsigned sup = 0;
                for (int w = 0; w <= mywmax; w++)
                    sup |= mrow[w] & kw[cur][w];
                kp = myvalid && (sup == 0);
            }
            unsigned word = __ballot_sync(FULLM, kp);
            if (lane == 0 && wrp < NW) {
                kw[cur ^ 1][wrp] = word;
                if (word != kw[cur][wrp]) schanged = 1;
            }
            __syncthreads();
            if (!schanged) break;               // fixed point == greedy result
            cur ^= 1;
        }
        if (tid < NW) svalid[tid] = kw[cur][tid];
    }
    __syncthreads();

    // Outputs: [ids(4800) | boxes(19200) | labels(4800) | scores(4800) | keep(4800)]
    if (tid < NK) {
        bool keep = (svalid[tid >> 5] >> (tid & 31)) & 1u;
        int slot = b * NK + tid;
        float kf = keep ? 1.0f : 0.0f;
        float4 bx = sbox[tid];
        out[slot] = keep ? (float)b : -1.0f;
        float* ob = out + NB * NK + slot * 4;
        ob[0] = bx.x * kf;
        ob[1] = bx.y * kf;
        ob[2] = bx.z * kf;
        ob[3] = bx.w * kf;
        out[NB * NK * 5 + slot] = kf;
        out[NB * NK * 6 + slot] = ssc[tid] * kf;
        out[NB * NK * 7 + slot] = kf;
    }

    // Reset global scratch for next replay (module-load values also 0).
    for (int i = tid; i < NBINS; i += 1024) g_hist[b][i] = 0u;
    if (tid == 0) { g_count[b] = 0; g_done2[b] = 0; }
}

extern "C" void kernel_launch(void* const* d_in, const int* in_sizes, int n_in,
                              void* d_out, int out_size) {
    const float* p_loc   = (const float*)d_in[0];
    const float* p_conf  = (const float*)d_in[1];
    // d_in[2] = p_landms: dead compute in reference, intentionally unread.
    const float* anchors = (const float*)d_in[3];
    float* out = (float*)d_out;

    k_scan<<<(NB * NA / 4) / 256, 256>>>((const float4*)p_conf);
    k_select<<<NB * SEL_BLKS, 1024>>>(p_loc, anchors, out);
}